// round 2
// baseline (speedup 1.0000x reference)
#include <cuda_runtime.h>
#include <cstdint>
#include <cstdio>

#define BBATCH 16
#define NPTS   4096
#define SPTS   1024
#define D1C    256
#define D2C    512
#define CIN    768
#define C1C    512
#define C2C    256
#define MTOT   (BBATCH*NPTS)   // 65536

// ---------------- scratch (module-static device memory; no allocation) -------
__device__ float g_xcat[(size_t)MTOT * CIN];   // [M, 768] concat(points1, interp)
__device__ float g_h1  [(size_t)MTOT * C1C];   // [M, 512]
__device__ float g_h2  [(size_t)MTOT * C2C];   // [M, 256]
__device__ int   g_idx3[MTOT * 3];
__device__ float g_w3  [MTOT * 3];
__device__ float g_a1[C1C], g_bb1[C1C];
__device__ float g_a2[C2C], g_bb2[C2C];
__device__ float g_ar[C2C], g_bbr[C2C];

// ---------------- fold conv-bias + batchnorm into per-channel alpha/beta -----
// y = relu((dot + b - m) * g/sqrt(v+eps) + be) = relu(dot*alpha + beta)
__global__ void prep_kernel(
    const float* __restrict__ b1, const float* __restrict__ g1, const float* __restrict__ be1,
    const float* __restrict__ m1, const float* __restrict__ v1,
    const float* __restrict__ b2, const float* __restrict__ g2, const float* __restrict__ be2,
    const float* __restrict__ m2, const float* __restrict__ v2,
    const float* __restrict__ br, const float* __restrict__ gr, const float* __restrict__ ber,
    const float* __restrict__ mr, const float* __restrict__ vr)
{
    int i = threadIdx.x;
    if (i < C1C) {
        float a = g1[i] * rsqrtf(v1[i] + 1e-5f);
        g_a1[i] = a; g_bb1[i] = (b1[i] - m1[i]) * a + be1[i];
    }
    if (i < C2C) {
        float a2 = g2[i] * rsqrtf(v2[i] + 1e-5f);
        g_a2[i] = a2; g_bb2[i] = (b2[i] - m2[i]) * a2 + be2[i];
        float ar = gr[i] * rsqrtf(vr[i] + 1e-5f);
        g_ar[i] = ar; g_bbr[i] = (br[i] - mr[i]) * ar + ber[i];
    }
}

// ---------------- 3-NN over S=1024 candidates per query ----------------------
// Distance formula mirrors reference: |p|^2 + |q|^2 - 2 p.q
__global__ void knn_kernel(const float* __restrict__ xyz1, const float* __restrict__ xyz2)
{
    __shared__ float sx[SPTS], sy[SPTS], sz[SPTS], sn[SPTS];
    const int b = blockIdx.y;
    const int n = blockIdx.x * 128 + threadIdx.x;

    const float* q = xyz2 + (size_t)b * SPTS * 3;
    for (int s = threadIdx.x; s < SPTS; s += 128) {
        float x = q[s*3+0], y = q[s*3+1], z = q[s*3+2];
        sx[s] = x; sy[s] = y; sz[s] = z; sn[s] = x*x + y*y + z*z;
    }
    __syncthreads();

    const float* p = xyz1 + ((size_t)b * NPTS + n) * 3;
    const float px = p[0], py = p[1], pz = p[2];
    const float pn = px*px + py*py + pz*pz;

    float d0 = 3.4e38f, d1 = 3.4e38f, d2 = 3.4e38f;
    int   i0 = 0, i1 = 0, i2 = 0;
    #pragma unroll 4
    for (int s = 0; s < SPTS; s++) {
        float d = pn + sn[s] - 2.0f * (px*sx[s] + py*sy[s] + pz*sz[s]);
        if (d < d2) {
            if (d < d1) {
                d2 = d1; i2 = i1;
                if (d < d0) { d1 = d0; i1 = i0; d0 = d; i0 = s; }
                else        { d1 = d;  i1 = s; }
            } else { d2 = d; i2 = s; }
        }
    }
    float r0 = 1.0f / (d0 + 1e-8f);
    float r1 = 1.0f / (d1 + 1e-8f);
    float r2 = 1.0f / (d2 + 1e-8f);
    float inv = 1.0f / (r0 + r1 + r2);
    size_t o = ((size_t)b * NPTS + n) * 3;
    g_idx3[o+0] = i0; g_idx3[o+1] = i1; g_idx3[o+2] = i2;
    g_w3[o+0] = r0 * inv; g_w3[o+1] = r1 * inv; g_w3[o+2] = r2 * inv;
}

// ---------------- gather 3 rows of points2, blend, concat with points1 -------
__global__ void gather_kernel(const float* __restrict__ points1,
                              const float* __restrict__ points2)
{
    const int m = blockIdx.x;            // b*4096 + n
    const int b = m >> 12;
    const int t = threadIdx.x;           // 128 threads

    float* out = g_xcat + (size_t)m * CIN;
    const float4* p1 = (const float4*)(points1 + (size_t)m * D1C);
    if (t < D1C/4) ((float4*)out)[t] = p1[t];

    const size_t o3 = (size_t)m * 3;
    const int   i0 = g_idx3[o3+0], i1 = g_idx3[o3+1], i2 = g_idx3[o3+2];
    const float w0 = g_w3[o3+0],   w1 = g_w3[o3+1],   w2 = g_w3[o3+2];

    const float* base = points2 + (size_t)b * SPTS * D2C;
    const float4 a = ((const float4*)(base + (size_t)i0 * D2C))[t];
    const float4 c = ((const float4*)(base + (size_t)i1 * D2C))[t];
    const float4 e = ((const float4*)(base + (size_t)i2 * D2C))[t];
    float4 ov;
    ov.x = w0*a.x + w1*c.x + w2*e.x;
    ov.y = w0*a.y + w1*c.y + w2*e.y;
    ov.z = w0*a.z + w1*c.z + w2*e.z;
    ov.w = w0*a.w + w1*c.w + w2*e.w;
    ((float4*)(out + D1C))[t] = ov;
}

// ---------------- tiled SGEMM (NT): C[m,n] = relu(A[m,:].B[n,:] * al[n]+bt[n])
// 128x128 block tile, K-tile 16, 256 threads, 8x8 per-thread microtile.
template<bool RESID>
__global__ __launch_bounds__(256)
void sgemm_kernel(const float* __restrict__ A, const float* __restrict__ B,
                  const float* __restrict__ alpha, const float* __restrict__ beta,
                  const float* __restrict__ resid, float* __restrict__ C,
                  int K, int N)
{
    __shared__ float As[16][128];
    __shared__ float Bs[16][128];

    const int bm  = blockIdx.y * 128;
    const int bn  = blockIdx.x * 128;
    const int tid = threadIdx.x;
    const int tx  = tid & 15;            // 0..15 -> n microtile
    const int ty  = tid >> 4;            // 0..15 -> m microtile
    const int lrow = tid >> 2;           // 0..63
    const int lcol = (tid & 3) * 4;      // 0,4,8,12

    float acc[8][8];
    #pragma unroll
    for (int i = 0; i < 8; i++)
        #pragma unroll
        for (int j = 0; j < 8; j++) acc[i][j] = 0.0f;

    const float* Ag = A + (size_t)(bm + lrow) * K + lcol;
    const float* Bg = B + (size_t)(bn + lrow) * K + lcol;

    for (int k0 = 0; k0 < K; k0 += 16) {
        float4 a0 = *(const float4*)(Ag + k0);
        float4 a1 = *(const float4*)(Ag + (size_t)64 * K + k0);
        float4 b0 = *(const float4*)(Bg + k0);
        float4 b1 = *(const float4*)(Bg + (size_t)64 * K + k0);

        As[lcol+0][lrow] = a0.x; As[lcol+1][lrow] = a0.y;
        As[lcol+2][lrow] = a0.z; As[lcol+3][lrow] = a0.w;
        As[lcol+0][lrow+64] = a1.x; As[lcol+1][lrow+64] = a1.y;
        As[lcol+2][lrow+64] = a1.z; As[lcol+3][lrow+64] = a1.w;
        Bs[lcol+0][lrow] = b0.x; Bs[lcol+1][lrow] = b0.y;
        Bs[lcol+2][lrow] = b0.z; Bs[lcol+3][lrow] = b0.w;
        Bs[lcol+0][lrow+64] = b1.x; Bs[lcol+1][lrow+64] = b1.y;
        Bs[lcol+2][lrow+64] = b1.z; Bs[lcol+3][lrow+64] = b1.w;
        __syncthreads();

        #pragma unroll
        for (int kk = 0; kk < 16; kk++) {
            float a[8], bb[8];
            *(float4*)&a[0]  = *(const float4*)&As[kk][ty*8];
            *(float4*)&a[4]  = *(const float4*)&As[kk][ty*8+4];
            *(float4*)&bb[0] = *(const float4*)&Bs[kk][tx*8];
            *(float4*)&bb[4] = *(const float4*)&Bs[kk][tx*8+4];
            #pragma unroll
            for (int i = 0; i < 8; i++)
                #pragma unroll
                for (int j = 0; j < 8; j++)
                    acc[i][j] = fmaf(a[i], bb[j], acc[i][j]);
        }
        __syncthreads();
    }

    float al[8], bt[8];
    #pragma unroll
    for (int j = 0; j < 8; j++) {
        al[j] = alpha[bn + tx*8 + j];
        bt[j] = beta [bn + tx*8 + j];
    }
    #pragma unroll
    for (int i = 0; i < 8; i++) {
        const int m = bm + ty*8 + i;
        float v[8];
        #pragma unroll
        for (int j = 0; j < 8; j++) {
            float x = fmaf(acc[i][j], al[j], bt[j]);
            x = fmaxf(x, 0.0f);                       // h = relu(bn(conv))
            if (RESID) {
                x += resid[(size_t)m * N + bn + tx*8 + j];
                x = fmaxf(x, 0.0f);                   // relu(h + x)
            }
            v[j] = x;
        }
        float* cp = C + (size_t)m * N + bn + tx*8;
        *(float4*)cp       = *(float4*)&v[0];
        *(float4*)(cp + 4) = *(float4*)&v[4];
    }
}

// ---------------------------------------------------------------------------
extern "C" void kernel_launch(void* const* d_in, const int* in_sizes, int n_in,
                              void* d_out, int out_size)
{
    (void)in_sizes; (void)n_in; (void)out_size;
    const float* xyz1    = (const float*)d_in[0];
    const float* xyz2    = (const float*)d_in[1];
    const float* points1 = (const float*)d_in[2];
    const float* points2 = (const float*)d_in[3];
    const float* w1  = (const float*)d_in[4];
    const float* b1  = (const float*)d_in[5];
    const float* g1  = (const float*)d_in[6];
    const float* be1 = (const float*)d_in[7];
    const float* m1  = (const float*)d_in[8];
    const float* v1  = (const float*)d_in[9];
    const float* w2  = (const float*)d_in[10];
    const float* b2  = (const float*)d_in[11];
    const float* g2  = (const float*)d_in[12];
    const float* be2 = (const float*)d_in[13];
    const float* m2  = (const float*)d_in[14];
    const float* v2  = (const float*)d_in[15];
    const float* wr  = (const float*)d_in[16];
    const float* br  = (const float*)d_in[17];
    const float* gr  = (const float*)d_in[18];
    const float* ber = (const float*)d_in[19];
    const float* mr  = (const float*)d_in[20];
    const float* vr  = (const float*)d_in[21];
    float* out = (float*)d_out;

    void *p_xcat, *p_h1, *p_h2, *p_a1, *p_bb1, *p_a2, *p_bb2, *p_ar, *p_bbr;
    cudaGetSymbolAddress(&p_xcat, g_xcat);
    cudaGetSymbolAddress(&p_h1,  g_h1);
    cudaGetSymbolAddress(&p_h2,  g_h2);
    cudaGetSymbolAddress(&p_a1,  g_a1);
    cudaGetSymbolAddress(&p_bb1, g_bb1);
    cudaGetSymbolAddress(&p_a2,  g_a2);
    cudaGetSymbolAddress(&p_bb2, g_bb2);
    cudaGetSymbolAddress(&p_ar,  g_ar);
    cudaGetSymbolAddress(&p_bbr, g_bbr);

    prep_kernel<<<1, 512>>>(b1, g1, be1, m1, v1,
                            b2, g2, be2, m2, v2,
                            br, gr, ber, mr, vr);

    knn_kernel<<<dim3(NPTS/128, BBATCH), 128>>>(xyz1, xyz2);

    gather_kernel<<<MTOT, 128>>>(points1, points2);

    // layer 1: [M,768] x [512,768]^T -> h1 [M,512]
    sgemm_kernel<false><<<dim3(C1C/128, MTOT/128), 256>>>(
        (const float*)p_xcat, w1, (const float*)p_a1, (const float*)p_bb1,
        nullptr, (float*)p_h1, CIN, C1C);

    // layer 2: [M,512] x [256,512]^T -> h2 [M,256]
    sgemm_kernel<false><<<dim3(C2C/128, MTOT/128), 256>>>(
        (const float*)p_h1, w2, (const float*)p_a2, (const float*)p_bb2,
        nullptr, (float*)p_h2, C1C, C2C);

    // layer 3 + residual: out = relu(relu(bn(h2 x wr^T)) + h2)
    sgemm_kernel<true><<<dim3(C2C/128, MTOT/128), 256>>>(
        (const float*)p_h2, wr, (const float*)p_ar, (const float*)p_bbr,
        (const float*)p_h2, out, C2C, C2C);
}

// round 6
// speedup vs baseline: 2.2763x; 2.2763x over previous
#include <cuda_runtime.h>
#include <cstdint>
#include <cstdio>

#define BBATCH 16
#define NPTS   4096
#define SPTS   1024
#define D1C    256
#define D2C    512
#define CIN    768
#define C1C    512
#define C2C    256
#define MTOT   (BBATCH*NPTS)   // 65536

// ---------------- scratch (module-static device memory; no allocation) -------
__device__ float g_xcat[(size_t)MTOT * CIN];   // [M, 768] concat(points1, interp)
__device__ float g_h1  [(size_t)MTOT * C1C];   // [M, 512]
__device__ float g_h2  [(size_t)MTOT * C2C];   // [M, 256]
__device__ int   g_idx3[MTOT * 3];
__device__ float g_w3  [MTOT * 3];
__device__ float g_a1[C1C], g_bb1[C1C];
__device__ float g_a2[C2C], g_bb2[C2C];
__device__ float g_ar[C2C], g_bbr[C2C];

// ---------------- fold conv-bias + batchnorm into per-channel alpha/beta -----
__global__ void prep_kernel(
    const float* __restrict__ b1, const float* __restrict__ g1, const float* __restrict__ be1,
    const float* __restrict__ m1, const float* __restrict__ v1,
    const float* __restrict__ b2, const float* __restrict__ g2, const float* __restrict__ be2,
    const float* __restrict__ m2, const float* __restrict__ v2,
    const float* __restrict__ br, const float* __restrict__ gr, const float* __restrict__ ber,
    const float* __restrict__ mr, const float* __restrict__ vr)
{
    int i = threadIdx.x;
    if (i < C1C) {
        float a = g1[i] * rsqrtf(v1[i] + 1e-5f);
        g_a1[i] = a; g_bb1[i] = (b1[i] - m1[i]) * a + be1[i];
    }
    if (i < C2C) {
        float a2 = g2[i] * rsqrtf(v2[i] + 1e-5f);
        g_a2[i] = a2; g_bb2[i] = (b2[i] - m2[i]) * a2 + be2[i];
        float ar = gr[i] * rsqrtf(vr[i] + 1e-5f);
        g_ar[i] = ar; g_bbr[i] = (br[i] - mr[i]) * ar + ber[i];
    }
}

// ---------------- 3-NN over S=1024 candidates per query ----------------------
__global__ void knn_kernel(const float* __restrict__ xyz1, const float* __restrict__ xyz2)
{
    __shared__ float sx[SPTS], sy[SPTS], sz[SPTS], sn[SPTS];
    const int b = blockIdx.y;
    const int n = blockIdx.x * 128 + threadIdx.x;

    const float* q = xyz2 + (size_t)b * SPTS * 3;
    for (int s = threadIdx.x; s < SPTS; s += 128) {
        float x = q[s*3+0], y = q[s*3+1], z = q[s*3+2];
        sx[s] = x; sy[s] = y; sz[s] = z; sn[s] = x*x + y*y + z*z;
    }
    __syncthreads();

    const float* p = xyz1 + ((size_t)b * NPTS + n) * 3;
    const float px = p[0], py = p[1], pz = p[2];
    const float pn = px*px + py*py + pz*pz;

    float d0 = 3.4e38f, d1 = 3.4e38f, d2 = 3.4e38f;
    int   i0 = 0, i1 = 0, i2 = 0;
    #pragma unroll 4
    for (int s = 0; s < SPTS; s++) {
        float d = pn + sn[s] - 2.0f * (px*sx[s] + py*sy[s] + pz*sz[s]);
        if (d < d2) {
            if (d < d1) {
                d2 = d1; i2 = i1;
                if (d < d0) { d1 = d0; i1 = i0; d0 = d; i0 = s; }
                else        { d1 = d;  i1 = s; }
            } else { d2 = d; i2 = s; }
        }
    }
    float r0 = 1.0f / (d0 + 1e-8f);
    float r1 = 1.0f / (d1 + 1e-8f);
    float r2 = 1.0f / (d2 + 1e-8f);
    float inv = 1.0f / (r0 + r1 + r2);
    size_t o = ((size_t)b * NPTS + n) * 3;
    g_idx3[o+0] = i0; g_idx3[o+1] = i1; g_idx3[o+2] = i2;
    g_w3[o+0] = r0 * inv; g_w3[o+1] = r1 * inv; g_w3[o+2] = r2 * inv;
}

// ---------------- gather 3 rows of points2, blend, concat with points1 -------
__global__ void gather_kernel(const float* __restrict__ points1,
                              const float* __restrict__ points2)
{
    const int m = blockIdx.x;            // b*4096 + n
    const int b = m >> 12;
    const int t = threadIdx.x;           // 128 threads

    float* out = g_xcat + (size_t)m * CIN;
    const float4* p1 = (const float4*)(points1 + (size_t)m * D1C);
    if (t < D1C/4) ((float4*)out)[t] = p1[t];

    const size_t o3 = (size_t)m * 3;
    const int   i0 = g_idx3[o3+0], i1 = g_idx3[o3+1], i2 = g_idx3[o3+2];
    const float w0 = g_w3[o3+0],   w1 = g_w3[o3+1],   w2 = g_w3[o3+2];

    const float* base = points2 + (size_t)b * SPTS * D2C;
    const float4 a = ((const float4*)(base + (size_t)i0 * D2C))[t];
    const float4 c = ((const float4*)(base + (size_t)i1 * D2C))[t];
    const float4 e = ((const float4*)(base + (size_t)i2 * D2C))[t];
    float4 ov;
    ov.x = w0*a.x + w1*c.x + w2*e.x;
    ov.y = w0*a.y + w1*c.y + w2*e.y;
    ov.z = w0*a.z + w1*c.z + w2*e.z;
    ov.w = w0*a.w + w1*c.w + w2*e.w;
    ((float4*)(out + D1C))[t] = ov;
}

// ================= TF32 tensor-core GEMM (NT) ================================
// C[m,n] = epilogue( sum_k A[m,k]*B[n,k] )
// 128x128 CTA tile, BK=32, 8 warps (2x4), warp tile 64x32, m16n8k8 tf32 mma.
// cp.async double-buffered smem, row-major padded tiles (stride 36 floats:
// fragment-load bank = (4*gr + gc) % 32 -> conflict-free).

#define BKT    32
#define LDT    36                       // padded row stride (floats)
#define TILE_F (128*LDT)                // floats per buffer per matrix

__device__ __forceinline__ uint32_t f2tf32(float x) {
    uint32_t r;
    asm("cvt.rna.tf32.f32 %0, %1;" : "=r"(r) : "f"(x));
    return r;
}

__device__ __forceinline__ void mma_tf32(float* d, const uint32_t* a, const uint32_t* b) {
    asm volatile(
        "mma.sync.aligned.m16n8k8.row.col.f32.tf32.tf32.f32 "
        "{%0,%1,%2,%3}, {%4,%5,%6,%7}, {%8,%9}, {%0,%1,%2,%3};"
        : "+f"(d[0]), "+f"(d[1]), "+f"(d[2]), "+f"(d[3])
        : "r"(a[0]), "r"(a[1]), "r"(a[2]), "r"(a[3]), "r"(b[0]), "r"(b[1]));
}

#define CP_ASYNC16(dst, src) \
    asm volatile("cp.async.cg.shared.global [%0], [%1], 16;" :: "r"(dst), "l"(src))

template<bool RESID>
__global__ __launch_bounds__(256, 2)
void tfgemm_kernel(const float* __restrict__ A, const float* __restrict__ B,
                   const float* __restrict__ alpha, const float* __restrict__ beta,
                   const float* __restrict__ resid, float* __restrict__ C,
                   int K, int N)
{
    extern __shared__ float smem[];
    float* As = smem;                    // [2][128][36]
    float* Bs = smem + 2 * TILE_F;       // [2][128][36]

    const int bm   = blockIdx.y * 128;
    const int bn   = blockIdx.x * 128;
    const int tid  = threadIdx.x;
    const int lane = tid & 31;
    const int warp = tid >> 5;
    const int wm   = (warp & 1) * 64;
    const int wn   = (warp >> 1) * 32;
    const int gr   = lane >> 2;          // 0..7
    const int gc   = lane & 3;           // 0..3

    // cp.async mapping: 2 threads per row, each copies 4x16B (16 floats)
    const int crow = tid >> 1;                 // 0..127
    const int ccol = (tid & 1) * 16;           // float offset in K
    const float* Ag = A + (size_t)(bm + crow) * K + ccol;
    const float* Bg = B + (size_t)(bn + crow) * K + ccol;
    const uint32_t sAbase = (uint32_t)__cvta_generic_to_shared(As) + (crow * LDT + ccol) * 4;
    const uint32_t sBbase = (uint32_t)__cvta_generic_to_shared(Bs) + (crow * LDT + ccol) * 4;
    const uint32_t bufBytes = TILE_F * 4;

    float acc[4][4][4];
    #pragma unroll
    for (int mi = 0; mi < 4; mi++)
        #pragma unroll
        for (int ni = 0; ni < 4; ni++)
            #pragma unroll
            for (int r = 0; r < 4; r++) acc[mi][ni][r] = 0.0f;

    const int T = K / BKT;

    // prologue: stage tile 0 into buffer 0
    {
        const float* ag = Ag;
        const float* bg = Bg;
        #pragma unroll
        for (int j = 0; j < 4; j++) {
            CP_ASYNC16(sAbase + j * 16, ag + j * 4);
            CP_ASYNC16(sBbase + j * 16, bg + j * 4);
        }
        asm volatile("cp.async.commit_group;");
    }

    for (int t = 0; t < T; t++) {
        if (t + 1 < T) {
            const int nb = (t + 1) & 1;
            const float* ag = Ag + (t + 1) * BKT;
            const float* bg = Bg + (t + 1) * BKT;
            const uint32_t da = sAbase + nb * bufBytes;
            const uint32_t db = sBbase + nb * bufBytes;
            #pragma unroll
            for (int j = 0; j < 4; j++) {
                CP_ASYNC16(da + j * 16, ag + j * 4);
                CP_ASYNC16(db + j * 16, bg + j * 4);
            }
            asm volatile("cp.async.commit_group;");
            asm volatile("cp.async.wait_group 1;");
        } else {
            asm volatile("cp.async.wait_group 0;");
        }
        __syncthreads();

        const float* Ab = As + (t & 1) * TILE_F;
        const float* Bb = Bs + (t & 1) * TILE_F;

        #pragma unroll
        for (int ks = 0; ks < 4; ks++) {
            const int k0 = ks * 8;
            uint32_t af[4][4];
            #pragma unroll
            for (int mi = 0; mi < 4; mi++) {
                const int m = wm + mi * 16 + gr;
                af[mi][0] = f2tf32(Ab[(m    ) * LDT + k0 + gc    ]);
                af[mi][1] = f2tf32(Ab[(m + 8) * LDT + k0 + gc    ]);
                af[mi][2] = f2tf32(Ab[(m    ) * LDT + k0 + gc + 4]);
                af[mi][3] = f2tf32(Ab[(m + 8) * LDT + k0 + gc + 4]);
            }
            uint32_t bf[4][2];
            #pragma unroll
            for (int ni = 0; ni < 4; ni++) {
                const int n = wn + ni * 8 + gr;
                bf[ni][0] = f2tf32(Bb[n * LDT + k0 + gc    ]);
                bf[ni][1] = f2tf32(Bb[n * LDT + k0 + gc + 4]);
            }
            #pragma unroll
            for (int mi = 0; mi < 4; mi++)
                #pragma unroll
                for (int ni = 0; ni < 4; ni++)
                    mma_tf32(acc[mi][ni], af[mi], bf[ni]);
        }
        __syncthreads();
    }

    // epilogue: y = relu(acc*alpha + beta) [+ resid, relu]
    #pragma unroll
    for (int ni = 0; ni < 4; ni++) {
        const int n = bn + wn + ni * 8 + 2 * gc;
        const float al0 = alpha[n],     bt0 = beta[n];
        const float al1 = alpha[n + 1], bt1 = beta[n + 1];
        #pragma unroll
        for (int mi = 0; mi < 4; mi++) {
            const int m0 = bm + wm + mi * 16 + gr;
            const int m1 = m0 + 8;
            float x0 = fmaxf(fmaf(acc[mi][ni][0], al0, bt0), 0.0f);
            float x1 = fmaxf(fmaf(acc[mi][ni][1], al1, bt1), 0.0f);
            float x2 = fmaxf(fmaf(acc[mi][ni][2], al0, bt0), 0.0f);
            float x3 = fmaxf(fmaf(acc[mi][ni][3], al1, bt1), 0.0f);
            if (RESID) {
                const float2 r0 = *(const float2*)(resid + (size_t)m0 * N + n);
                const float2 r1 = *(const float2*)(resid + (size_t)m1 * N + n);
                x0 = fmaxf(x0 + r0.x, 0.0f);
                x1 = fmaxf(x1 + r0.y, 0.0f);
                x2 = fmaxf(x2 + r1.x, 0.0f);
                x3 = fmaxf(x3 + r1.y, 0.0f);
            }
            *(float2*)(C + (size_t)m0 * N + n) = make_float2(x0, x1);
            *(float2*)(C + (size_t)m1 * N + n) = make_float2(x2, x3);
        }
    }
}

// ---------------------------------------------------------------------------
extern "C" void kernel_launch(void* const* d_in, const int* in_sizes, int n_in,
                              void* d_out, int out_size)
{
    (void)in_sizes; (void)n_in; (void)out_size;
    const float* xyz1    = (const float*)d_in[0];
    const float* xyz2    = (const float*)d_in[1];
    const float* points1 = (const float*)d_in[2];
    const float* points2 = (const float*)d_in[3];
    const float* w1  = (const float*)d_in[4];
    const float* b1  = (const float*)d_in[5];
    const float* g1  = (const float*)d_in[6];
    const float* be1 = (const float*)d_in[7];
    const float* m1  = (const float*)d_in[8];
    const float* v1  = (const float*)d_in[9];
    const float* w2  = (const float*)d_in[10];
    const float* b2  = (const float*)d_in[11];
    const float* g2  = (const float*)d_in[12];
    const float* be2 = (const float*)d_in[13];
    const float* m2  = (const float*)d_in[14];
    const float* v2  = (const float*)d_in[15];
    const float* wr  = (const float*)d_in[16];
    const float* br  = (const float*)d_in[17];
    const float* gr  = (const float*)d_in[18];
    const float* ber = (const float*)d_in[19];
    const float* mr  = (const float*)d_in[20];
    const float* vr  = (const float*)d_in[21];
    float* out = (float*)d_out;

    void *p_xcat, *p_h1, *p_h2, *p_a1, *p_bb1, *p_a2, *p_bb2, *p_ar, *p_bbr;
    cudaGetSymbolAddress(&p_xcat, g_xcat);
    cudaGetSymbolAddress(&p_h1,  g_h1);
    cudaGetSymbolAddress(&p_h2,  g_h2);
    cudaGetSymbolAddress(&p_a1,  g_a1);
    cudaGetSymbolAddress(&p_bb1, g_bb1);
    cudaGetSymbolAddress(&p_a2,  g_a2);
    cudaGetSymbolAddress(&p_bb2, g_bb2);
    cudaGetSymbolAddress(&p_ar,  g_ar);
    cudaGetSymbolAddress(&p_bbr, g_bbr);

    const int smemBytes = 4 * TILE_F * 4;   // 2 matrices x 2 buffers = 73728 B
    cudaFuncSetAttribute(tfgemm_kernel<false>,
                         cudaFuncAttributeMaxDynamicSharedMemorySize, smemBytes);
    cudaFuncSetAttribute(tfgemm_kernel<true>,
                         cudaFuncAttributeMaxDynamicSharedMemorySize, smemBytes);

    prep_kernel<<<1, 512>>>(b1, g1, be1, m1, v1,
                            b2, g2, be2, m2, v2,
                            br, gr, ber, mr, vr);

    knn_kernel<<<dim3(NPTS/128, BBATCH), 128>>>(xyz1, xyz2);

    gather_kernel<<<MTOT, 128>>>(points1, points2);

    // layer 1: [M,768] x [512,768]^T -> h1 [M,512]
    tfgemm_kernel<false><<<dim3(C1C/128, MTOT/128), 256, smemBytes>>>(
        (const float*)p_xcat, w1, (const float*)p_a1, (const float*)p_bb1,
        nullptr, (float*)p_h1, CIN, C1C);

    // layer 2: [M,512] x [256,512]^T -> h2 [M,256]
    tfgemm_kernel<false><<<dim3(C2C/128, MTOT/128), 256, smemBytes>>>(
        (const float*)p_h1, w2, (const float*)p_a2, (const float*)p_bb2,
        nullptr, (float*)p_h2, C1C, C2C);

    // layer 3 + residual: out = relu(relu(bn(h2 x wr^T)) + h2)
    tfgemm_kernel<true><<<dim3(C2C/128, MTOT/128), 256, smemBytes>>>(
        (const float*)p_h2, wr, (const float*)p_ar, (const float*)p_bbr,
        (const float*)p_h2, out, C2C, C2C);
}